// round 5
// baseline (speedup 1.0000x reference)
#include <cuda_runtime.h>
#include <math.h>

// ---------------- problem constants ----------------
// B=4, C=3, H=W=768, P=128, S=64, K=31, n_h=n_w=11, N=121
#define TOTAL   7077888          // 4*3*768*768
#define IMGHW   589824           // 768*768
#define NPIX    961              // 31*31

// ---------------- device scratch ----------------
__device__ float g_basis[14 * NPIX];
__device__ float g_mask[NPIX];
__device__ float g_coeffs[121 * 14];
__device__ float g_kern[363 * NPIX];      // flipped+normalized PSFs, [n*3+c][31*31]
__device__ float g_xlin[TOTAL];           // (relu(x)+eps)^gamma
__device__ float g_acc[4 * TOTAL];        // 4 parity planes for overlap-add

__device__ __forceinline__ float hann128(int r) {
    return 0.5f * (1.0f - cosf((6.28318530717958647692f * (float)r) * 0.0078125f));
}

__device__ __forceinline__ double dpow_i(double x, int e) {
    double r = 1.0;
    for (int q = 0; q < e; q++) r *= x;
    return r;
}

// ---------------- stage 0: pupil basis ----------------
// CRITICAL: replicate numpy's exact IEEE op sequence (no FMA contraction!) for the
// linspace values and r2, because 31x31 grid has 16 pixels EXACTLY on r2==1
// (9-12-15 Pythagorean triple) whose mask membership is decided by last-ulp rounding.
__global__ void basis_kernel() {
    __shared__ float red[1024];
    int t = threadIdx.x;
    bool act = (t < NPIX);
    int i = t / 31, j = t % 31;

    double step = 2.0 / 30.0;   // rn(2/30), matches numpy linspace delta
    double x = 0.0, y = 0.0;
    float m = 0.0f;
    if (act) {
        // numpy linspace: y = rn(rn(j*delta) + start); y[-1] = stop
        x = (j == 30) ? 1.0 : __dadd_rn(__dmul_rn((double)j, step), -1.0);
        y = (i == 30) ? 1.0 : __dadd_rn(__dmul_rn((double)i, step), -1.0);
        // numpy: rn(rn(x^2) + rn(y^2)) — separate ufuncs, NO fma
        double r2 = __dadd_rn(__dmul_rn(x, x), __dmul_rn(y, y));
        m = (r2 <= 1.0) ? 1.0f : 0.0f;
        g_mask[t] = m;
    }
    red[t] = act ? m : 0.0f;
    __syncthreads();
    for (int s = 512; s > 0; s >>= 1) {
        if (t < s) red[t] += red[t + s];
        __syncthreads();
    }
    float mc = red[0];
    __syncthreads();

    int z = 0;
    for (int deg = 1; deg <= 4; deg++) {
        for (int k = 0; k <= deg; k++) {
            float bb = 0.0f;
            if (act) bb = (float)(dpow_i(x, deg - k) * dpow_i(y, k)) * m;
            red[t] = bb * bb;
            __syncthreads();
            for (int s = 512; s > 0; s >>= 1) {
                if (t < s) red[t] += red[t + s];
                __syncthreads();
            }
            float rms = sqrtf(red[0] / mc) + 1e-8f;
            __syncthreads();
            if (act) g_basis[z * NPIX + t] = bb / rms;
            z++;
        }
    }
}

// ---------------- stage 1: MLP -> zernike coeffs ----------------
__global__ void mlp_kernel(const float* __restrict__ w1, const float* __restrict__ b1,
                           const float* __restrict__ w2, const float* __restrict__ b2,
                           const float* __restrict__ w3, const float* __restrict__ b3) {
    __shared__ float s1[64], s2[64];
    int n = blockIdx.x;       // 0..120
    int t = threadIdx.x;      // 0..63
    int iy = n / 11, jx = n % 11;
    float cy = (float)((((double)(iy * 64) + 64.0) / 768.0) * 2.0 - 1.0);
    float cx = (float)((((double)(jx * 64) + 64.0) / 768.0) * 2.0 - 1.0);

    float h = tanhf(cy * w1[t] + cx * w1[64 + t] + b1[t]);
    s1[t] = h;
    __syncthreads();
    float a = b2[t];
    for (int k = 0; k < 64; k++) a += s1[k] * w2[k * 64 + t];
    s2[t] = tanhf(a);
    __syncthreads();
    if (t < 14) {
        float o = b3[t];
        for (int k = 0; k < 64; k++) o += s2[k] * w3[k * 14 + t];
        g_coeffs[n * 14 + t] = o;
    }
}

// ---------------- stage 2: PSF via 31x31 separable DFT ----------------
__global__ void psf_kernel() {
    __shared__ float fre[NPIX], fim[NPIX], Gre[NPIX], Gim[NPIX];
    __shared__ float twr[31], twi[31];
    __shared__ float red[1024];
    int t = threadIdx.x;
    bool act = (t < NPIX);
    int blk = blockIdx.x;            // n*3 + c
    int n = blk / 3, c = blk % 3;

    if (t < 31) {
        float ang = -6.28318530717958647692f * (float)t / 31.0f;
        twr[t] = cosf(ang);
        twi[t] = sinf(ang);
    }
    float wl = 0.53f / ((c == 0) ? 0.61f : ((c == 1) ? 0.53f : 0.47f));

    if (act) {
        float ph = 0.0f;
        const float* cf = &g_coeffs[n * 14];
#pragma unroll
        for (int z = 0; z < 14; z++) ph = fmaf(cf[z], g_basis[z * NPIX + t], ph);
        float th = 6.28318530717958647692f * (wl * ph);
        float sn, cs;
        sincosf(th, &sn, &cs);
        float m = g_mask[t];
        fre[t] = m * cs;
        fim[t] = m * sn;
    }
    __syncthreads();

    int u = t / 31, v = t % 31;
    if (act) {
        float gr = 0.0f, gi = 0.0f;
        int m2 = 0;
        for (int i2 = 0; i2 < 31; i2++) {
            float tr = twr[m2], ti = twi[m2];
            float ar = fre[i2 * 31 + v], ai = fim[i2 * 31 + v];
            gr = fmaf(ar, tr, gr); gr = fmaf(-ai, ti, gr);
            gi = fmaf(ar, ti, gi); gi = fmaf(ai, tr, gi);
            m2 += u; if (m2 >= 31) m2 -= 31;
        }
        Gre[t] = gr; Gim[t] = gi;
    }
    __syncthreads();

    float mag = 0.0f;
    if (act) {
        float fr = 0.0f, fi = 0.0f;
        int m2 = 0;
        for (int j2 = 0; j2 < 31; j2++) {
            float tr = twr[m2], ti = twi[m2];
            float gr = Gre[u * 31 + j2], gi = Gim[u * 31 + j2];
            fr = fmaf(gr, tr, fr); fr = fmaf(-gi, ti, fr);
            fi = fmaf(gr, ti, fi); fi = fmaf(gi, tr, fi);
            m2 += v; if (m2 >= 31) m2 -= 31;
        }
        mag = fr * fr + fi * fi;
    }
    red[t] = act ? mag : 0.0f;
    __syncthreads();
    for (int s = 512; s > 0; s >>= 1) {
        if (t < s) red[t] += red[t + s];
        __syncthreads();
    }
    float inv = 1.0f / (red[0] + 1e-6f);
    if (act) {
        int pu = u + 15; if (pu >= 31) pu -= 31;   // fftshift
        int pv = v + 15; if (pv >= 31) pv -= 31;
        g_kern[blk * NPIX + (30 - pu) * 31 + (30 - pv)] = mag * inv;  // flip (confirmed by R4)
    }
}

// ---------------- stage 3: gamma-linearize + zero accumulators ----------------
__global__ void prep_kernel(const float* __restrict__ x, const float* __restrict__ gp) {
    int id = blockIdx.x * blockDim.x + threadIdx.x;
    if (id >= TOTAL) return;
    float g = *gp;
    float v = x[id];
    g_xlin[id] = powf(fmaxf(v, 0.0f) + 1e-6f, g);
    g_acc[id] = 0.0f;
    g_acc[TOTAL + id] = 0.0f;
    g_acc[2 * TOTAL + id] = 0.0f;
    g_acc[3 * TOTAL + id] = 0.0f;
}

// ---------------- stage 4: the heavy 31x31 depthwise conv (register ring buffer) ----------------
__global__ void __launch_bounds__(256) conv_kernel() {
    __shared__ float sIn[94 * 62];
    __shared__ float sK[NPIX];

    int id = blockIdx.x;
    int tile = id & 7;
    int pcc = id >> 3;
    int c = pcc % 3;
    int t2 = pcc / 3;
    int n = t2 % 121;
    int b = t2 / 121;
    int ip = n / 11, jp = n % 11;
    int R0 = (tile >> 2) << 6;   // 0 or 64
    int C0 = (tile & 3) << 5;    // 0,32,64,96
    int tid = threadIdx.x;

    const float* gk = g_kern + (n * 3 + c) * NPIX;
    for (int q = tid; q < NPIX; q += 256) sK[q] = gk[q];

    const float* gxp = g_xlin + (size_t)(b * 3 + c) * IMGHW;
    for (int q = tid; q < 94 * 62; q += 256) {
        int rr = q / 62;
        int cc = q - rr * 62;
        int sy = R0 + rr - 15;
        int sx = C0 + cc - 15;
        float v = 0.0f;
        if ((unsigned)sy < 128u && (unsigned)sx < 128u)
            v = gxp[(ip * 64 + sy) * 768 + (jp * 64 + sx)];
        sIn[q] = v;
    }
    __syncthreads();

    int tx = tid & 31, ty = tid >> 5;
    const float* pin = sIn + ty * 8 * 62 + tx;
    float acc[8];
#pragma unroll
    for (int i2 = 0; i2 < 8; i2++) acc[i2] = 0.0f;

#pragma unroll 1
    for (int dc = 0; dc < 31; ++dc) {
        const float* p = pin + dc;
        float w[8];
#pragma unroll
        for (int i2 = 0; i2 < 8; i2++) w[i2] = p[i2 * 62];
#pragma unroll
        for (int dr = 0; dr < 31; ++dr) {
            float kv = sK[dr * 31 + dc];
#pragma unroll
            for (int i2 = 0; i2 < 8; i2++)
                acc[i2] = fmaf(kv, w[(dr + i2) & 7], acc[i2]);
            if (dr < 30) w[dr & 7] = p[(dr + 8) * 62];
        }
    }

    int plane = ((ip & 1) << 1) | (jp & 1);
    float hc = hann128(C0 + tx);
    int gx0 = jp * 64 + C0 + tx;
    float* outp = g_acc + (size_t)plane * TOTAL + (size_t)(b * 3 + c) * IMGHW;
#pragma unroll
    for (int i2 = 0; i2 < 8; i2++) {
        int pr = R0 + ty * 8 + i2;
        int gy = ip * 64 + pr;
        outp[gy * 768 + gx0] = acc[i2] * (hann128(pr) * hc);
    }
}

// ---------------- stage 5: gather planes, window-normalize, inverse gamma ----------------
__global__ void fin_kernel(float* __restrict__ out, const float* __restrict__ gp) {
    int id = blockIdx.x * blockDim.x + threadIdx.x;
    if (id >= TOTAL) return;
    float ig = 1.0f / (*gp);
    int xcol = id % 768;
    int y = (id / 768) % 768;

    float ny = 0.0f, nx = 0.0f;
    int i1 = y >> 6;
    if (i1 <= 10) ny += hann128(y - i1 * 64);
    if (i1 >= 1)  ny += hann128(y - (i1 - 1) * 64);
    int j1 = xcol >> 6;
    if (j1 <= 10) nx += hann128(xcol - j1 * 64);
    if (j1 >= 1)  nx += hann128(xcol - (j1 - 1) * 64);

    float s = g_acc[id] + g_acc[TOTAL + id] + g_acc[2 * TOTAL + id] + g_acc[3 * TOTAL + id];
    float v = s / (ny * nx + 1e-6f);
    out[id] = powf(fmaxf(v, 0.0f) + 1e-6f, ig);
}

// ---------------- launch ----------------
extern "C" void kernel_launch(void* const* d_in, const int* in_sizes, int n_in,
                              void* d_out, int out_size) {
    const float* x  = (const float*)d_in[0];
    const float* w1 = (const float*)d_in[1];
    const float* b1 = (const float*)d_in[2];
    const float* w2 = (const float*)d_in[3];
    const float* b2 = (const float*)d_in[4];
    const float* w3 = (const float*)d_in[5];
    const float* b3 = (const float*)d_in[6];
    const float* gp = (const float*)d_in[7];
    float* out = (float*)d_out;

    basis_kernel<<<1, 1024>>>();
    mlp_kernel<<<121, 64>>>(w1, b1, w2, b2, w3, b3);
    psf_kernel<<<363, 1024>>>();
    prep_kernel<<<(TOTAL + 255) / 256, 256>>>(x, gp);
    conv_kernel<<<11616, 256>>>();
    fin_kernel<<<(TOTAL + 255) / 256, 256>>>(out, gp);
}

// round 6
// speedup vs baseline: 1.0170x; 1.0170x over previous
#include <cuda_runtime.h>
#include <math.h>

// ---------------- problem constants ----------------
// B=4, C=3, H=W=768, P=128, S=64, K=31, n_h=n_w=11, N=121
#define TOTAL   7077888          // 4*3*768*768
#define IMGHW   589824           // 768*768
#define NPIX    961              // 31*31

typedef unsigned long long u64;

// ---------------- device scratch ----------------
__device__ float g_basis[14 * NPIX];
__device__ float g_mask[NPIX];
__device__ float g_coeffs[121 * 14];
__device__ float g_kern[363 * NPIX];      // flipped+normalized PSFs, [n*3+c][31*31]
__device__ float g_xlin[TOTAL];           // (relu(x)+eps)^gamma
__device__ float g_acc[4 * TOTAL];        // 4 parity planes (zero-init .bss; only valid entries ever written)

__device__ __forceinline__ float hann128(int r) {
    return 0.5f * (1.0f - cosf((6.28318530717958647692f * (float)r) * 0.0078125f));
}

__device__ __forceinline__ double dpow_i(double x, int e) {
    double r = 1.0;
    for (int q = 0; q < e; q++) r *= x;
    return r;
}

// packed 2xfp32 FMA (sm_103a FFMA2)
__device__ __forceinline__ void ffma2(u64& acc, u64 k2, u64 w2) {
    asm("fma.rn.f32x2 %0, %1, %2, %0;" : "+l"(acc) : "l"(k2), "l"(w2));
}
__device__ __forceinline__ float u64lo(u64 v) { return __uint_as_float((unsigned)v); }
__device__ __forceinline__ float u64hi(u64 v) { return __uint_as_float((unsigned)(v >> 32)); }

// ---------------- stage 0: pupil basis ----------------
// CRITICAL: replicate numpy's exact IEEE op sequence (no FMA contraction!) — 16 pixels
// sit EXACTLY on r2==1 (9-12-15 triple); membership decided by last-ulp rounding.
__global__ void basis_kernel() {
    __shared__ float red[1024];
    int t = threadIdx.x;
    bool act = (t < NPIX);
    int i = t / 31, j = t % 31;

    double step = 2.0 / 30.0;
    double x = 0.0, y = 0.0;
    float m = 0.0f;
    if (act) {
        x = (j == 30) ? 1.0 : __dadd_rn(__dmul_rn((double)j, step), -1.0);
        y = (i == 30) ? 1.0 : __dadd_rn(__dmul_rn((double)i, step), -1.0);
        double r2 = __dadd_rn(__dmul_rn(x, x), __dmul_rn(y, y));
        m = (r2 <= 1.0) ? 1.0f : 0.0f;
        g_mask[t] = m;
    }
    red[t] = act ? m : 0.0f;
    __syncthreads();
    for (int s = 512; s > 0; s >>= 1) {
        if (t < s) red[t] += red[t + s];
        __syncthreads();
    }
    float mc = red[0];
    __syncthreads();

    int z = 0;
    for (int deg = 1; deg <= 4; deg++) {
        for (int k = 0; k <= deg; k++) {
            float bb = 0.0f;
            if (act) bb = (float)(dpow_i(x, deg - k) * dpow_i(y, k)) * m;
            red[t] = bb * bb;
            __syncthreads();
            for (int s = 512; s > 0; s >>= 1) {
                if (t < s) red[t] += red[t + s];
                __syncthreads();
            }
            float rms = sqrtf(red[0] / mc) + 1e-8f;
            __syncthreads();
            if (act) g_basis[z * NPIX + t] = bb / rms;
            z++;
        }
    }
}

// ---------------- stage 1: MLP -> zernike coeffs ----------------
__global__ void mlp_kernel(const float* __restrict__ w1, const float* __restrict__ b1,
                           const float* __restrict__ w2, const float* __restrict__ b2,
                           const float* __restrict__ w3, const float* __restrict__ b3) {
    __shared__ float s1[64], s2[64];
    int n = blockIdx.x;
    int t = threadIdx.x;
    int iy = n / 11, jx = n % 11;
    float cy = (float)((((double)(iy * 64) + 64.0) / 768.0) * 2.0 - 1.0);
    float cx = (float)((((double)(jx * 64) + 64.0) / 768.0) * 2.0 - 1.0);

    float h = tanhf(cy * w1[t] + cx * w1[64 + t] + b1[t]);
    s1[t] = h;
    __syncthreads();
    float a = b2[t];
    for (int k = 0; k < 64; k++) a += s1[k] * w2[k * 64 + t];
    s2[t] = tanhf(a);
    __syncthreads();
    if (t < 14) {
        float o = b3[t];
        for (int k = 0; k < 64; k++) o += s2[k] * w3[k * 14 + t];
        g_coeffs[n * 14 + t] = o;
    }
}

// ---------------- stage 2: PSF via 31x31 separable DFT ----------------
__global__ void psf_kernel() {
    __shared__ float fre[NPIX], fim[NPIX], Gre[NPIX], Gim[NPIX];
    __shared__ float twr[31], twi[31];
    __shared__ float red[1024];
    int t = threadIdx.x;
    bool act = (t < NPIX);
    int blk = blockIdx.x;            // n*3 + c
    int n = blk / 3, c = blk % 3;

    if (t < 31) {
        float ang = -6.28318530717958647692f * (float)t / 31.0f;
        twr[t] = cosf(ang);
        twi[t] = sinf(ang);
    }
    float wl = 0.53f / ((c == 0) ? 0.61f : ((c == 1) ? 0.53f : 0.47f));

    if (act) {
        float ph = 0.0f;
        const float* cf = &g_coeffs[n * 14];
#pragma unroll
        for (int z = 0; z < 14; z++) ph = fmaf(cf[z], g_basis[z * NPIX + t], ph);
        float th = 6.28318530717958647692f * (wl * ph);
        float sn, cs;
        sincosf(th, &sn, &cs);
        float m = g_mask[t];
        fre[t] = m * cs;
        fim[t] = m * sn;
    }
    __syncthreads();

    int u = t / 31, v = t % 31;
    if (act) {
        float gr = 0.0f, gi = 0.0f;
        int m2 = 0;
        for (int i2 = 0; i2 < 31; i2++) {
            float tr = twr[m2], ti = twi[m2];
            float ar = fre[i2 * 31 + v], ai = fim[i2 * 31 + v];
            gr = fmaf(ar, tr, gr); gr = fmaf(-ai, ti, gr);
            gi = fmaf(ar, ti, gi); gi = fmaf(ai, tr, gi);
            m2 += u; if (m2 >= 31) m2 -= 31;
        }
        Gre[t] = gr; Gim[t] = gi;
    }
    __syncthreads();

    float mag = 0.0f;
    if (act) {
        float fr = 0.0f, fi = 0.0f;
        int m2 = 0;
        for (int j2 = 0; j2 < 31; j2++) {
            float tr = twr[m2], ti = twi[m2];
            float gr = Gre[u * 31 + j2], gi = Gim[u * 31 + j2];
            fr = fmaf(gr, tr, fr); fr = fmaf(-gi, ti, fr);
            fi = fmaf(gr, ti, fi); fi = fmaf(gi, tr, fi);
            m2 += v; if (m2 >= 31) m2 -= 31;
        }
        mag = fr * fr + fi * fi;
    }
    red[t] = act ? mag : 0.0f;
    __syncthreads();
    for (int s = 512; s > 0; s >>= 1) {
        if (t < s) red[t] += red[t + s];
        __syncthreads();
    }
    float inv = 1.0f / (red[0] + 1e-6f);
    if (act) {
        int pu = u + 15; if (pu >= 31) pu -= 31;
        int pv = v + 15; if (pv >= 31) pv -= 31;
        g_kern[blk * NPIX + (30 - pu) * 31 + (30 - pv)] = mag * inv;
    }
}

// ---------------- stage 3: gamma-linearize (no zeroing needed) ----------------
__global__ void prep_kernel(const float* __restrict__ x, const float* __restrict__ gp) {
    int id = blockIdx.x * blockDim.x + threadIdx.x;
    if (id >= TOTAL) return;
    float g = *gp;
    float v = x[id];
    g_xlin[id] = powf(fmaxf(v, 0.0f) + 1e-6f, g);
}

// ---------------- stage 4: 31x31 depthwise conv with packed f32x2 FMA ----------------
// Thread = 8 output rows x 1 col. Even taps -> A[i]=(out[2i],out[2i+1]);
// odd taps -> shifted accumulators O[i]=(out[2i-1],out[2i]) consuming the SAME
// even-aligned input pairs (no odd-alignment packing needed). Input transposed in
// smem so row pairs are aligned LDS.64 (stride 94 floats = 47 u64, odd => conflict-free).
__global__ void __launch_bounds__(256) conv_kernel() {
    __shared__ float sInT[62 * 94];       // [col][row], 23.3 KB
    __shared__ float2 sKd[31 * 32];       // duplicated taps (k,k), [dc][dr], 7.9 KB

    int id = blockIdx.x;
    int tile = id & 7;
    int pcc = id >> 3;
    int c = pcc % 3;
    int t2 = pcc / 3;
    int n = t2 % 121;
    int b = t2 / 121;
    int ip = n / 11, jp = n % 11;
    int R0 = (tile >> 2) << 6;   // 0 or 64
    int C0 = (tile & 3) << 5;    // 0,32,64,96
    int tid = threadIdx.x;

    const float* gk = g_kern + (n * 3 + c) * NPIX;
    for (int q = tid; q < NPIX; q += 256) {
        int dr = q / 31, dc2 = q - dr * 31;
        float k = gk[q];
        sKd[dc2 * 32 + dr] = make_float2(k, k);
    }

    const float* gxp = g_xlin + (size_t)(b * 3 + c) * IMGHW;
    for (int q = tid; q < 94 * 62; q += 256) {
        int rr = q / 62;
        int cc = q - rr * 62;
        int sy = R0 + rr - 15;
        int sx = C0 + cc - 15;
        float v = 0.0f;
        if ((unsigned)sy < 128u && (unsigned)sx < 128u)
            v = gxp[(ip * 64 + sy) * 768 + (jp * 64 + sx)];
        sInT[cc * 94 + rr] = v;
    }
    __syncthreads();

    int tx = tid & 31, ty = tid >> 5;
    u64 A0 = 0, A1 = 0, A2 = 0, A3 = 0;
    u64 O0 = 0, O1 = 0, O2 = 0, O3 = 0, O4 = 0;

#pragma unroll 1
    for (int dc = 0; dc < 31; ++dc) {
        const u64* colp = (const u64*)(sInT + (tx + dc) * 94) + ty * 4;  // P_e[j] = colp[j]
        const u64* kp = (const u64*)(sKd + dc * 32);                     // (k[dr],k[dr])
        u64 pe[8];
#pragma unroll
        for (int j = 0; j < 7; j++) pe[j] = colp[j];

#pragma unroll
        for (int d = 0; d < 15; d++) {
            u64 ke = kp[2 * d];
            ffma2(A0, ke, pe[(d + 0) & 7]);
            ffma2(A1, ke, pe[(d + 1) & 7]);
            ffma2(A2, ke, pe[(d + 2) & 7]);
            ffma2(A3, ke, pe[(d + 3) & 7]);
            u64 ko = kp[2 * d + 1];
            ffma2(O0, ko, pe[(d + 0) & 7]);
            ffma2(O1, ko, pe[(d + 1) & 7]);
            ffma2(O2, ko, pe[(d + 2) & 7]);
            ffma2(O3, ko, pe[(d + 3) & 7]);
            ffma2(O4, ko, pe[(d + 4) & 7]);
            if (d + 7 < 19) pe[(d + 7) & 7] = colp[d + 7];
        }
        {
            u64 ke = kp[30];  // d = 15, even only
            ffma2(A0, ke, pe[(15 + 0) & 7]);
            ffma2(A1, ke, pe[(15 + 1) & 7]);
            ffma2(A2, ke, pe[(15 + 2) & 7]);
            ffma2(A3, ke, pe[(15 + 3) & 7]);
        }
    }

    // recombine even/odd halves: out[2i] = A[i].lo + O[i].hi ; out[2i+1] = A[i].hi + O[i+1].lo
    float outv[8];
    outv[0] = u64lo(A0) + u64hi(O0);
    outv[1] = u64hi(A0) + u64lo(O1);
    outv[2] = u64lo(A1) + u64hi(O1);
    outv[3] = u64hi(A1) + u64lo(O2);
    outv[4] = u64lo(A2) + u64hi(O2);
    outv[5] = u64hi(A2) + u64lo(O3);
    outv[6] = u64lo(A3) + u64hi(O3);
    outv[7] = u64hi(A3) + u64lo(O4);

    int plane = ((ip & 1) << 1) | (jp & 1);
    float hc = hann128(C0 + tx);
    int gx0 = jp * 64 + C0 + tx;
    float* outp = g_acc + (size_t)plane * TOTAL + (size_t)(b * 3 + c) * IMGHW;
#pragma unroll
    for (int i2 = 0; i2 < 8; i2++) {
        int pr = R0 + ty * 8 + i2;
        int gy = ip * 64 + pr;
        outp[gy * 768 + gx0] = outv[i2] * (hann128(pr) * hc);
    }
}

// ---------------- stage 5: gather planes, window-normalize, inverse gamma ----------------
__global__ void fin_kernel(float* __restrict__ out, const float* __restrict__ gp) {
    int id = blockIdx.x * blockDim.x + threadIdx.x;
    if (id >= TOTAL) return;
    float ig = 1.0f / (*gp);
    int xcol = id % 768;
    int y = (id / 768) % 768;

    float ny = 0.0f, nx = 0.0f;
    int i1 = y >> 6;
    if (i1 <= 10) ny += hann128(y - i1 * 64);
    if (i1 >= 1)  ny += hann128(y - (i1 - 1) * 64);
    int j1 = xcol >> 6;
    if (j1 <= 10) nx += hann128(xcol - j1 * 64);
    if (j1 >= 1)  nx += hann128(xcol - (j1 - 1) * 64);

    float s = g_acc[id] + g_acc[TOTAL + id] + g_acc[2 * TOTAL + id] + g_acc[3 * TOTAL + id];
    float v = s / (ny * nx + 1e-6f);
    out[id] = powf(fmaxf(v, 0.0f) + 1e-6f, ig);
}

// ---------------- launch ----------------
extern "C" void kernel_launch(void* const* d_in, const int* in_sizes, int n_in,
                              void* d_out, int out_size) {
    const float* x  = (const float*)d_in[0];
    const float* w1 = (const float*)d_in[1];
    const float* b1 = (const float*)d_in[2];
    const float* w2 = (const float*)d_in[3];
    const float* b2 = (const float*)d_in[4];
    const float* w3 = (const float*)d_in[5];
    const float* b3 = (const float*)d_in[6];
    const float* gp = (const float*)d_in[7];
    float* out = (float*)d_out;

    basis_kernel<<<1, 1024>>>();
    mlp_kernel<<<121, 64>>>(w1, b1, w2, b2, w3, b3);
    psf_kernel<<<363, 1024>>>();
    prep_kernel<<<(TOTAL + 255) / 256, 256>>>(x, gp);
    conv_kernel<<<11616, 256>>>();
    fin_kernel<<<(TOTAL + 255) / 256, 256>>>(out, gp);
}

// round 7
// speedup vs baseline: 1.1099x; 1.0914x over previous
#include <cuda_runtime.h>
#include <math.h>

// ---------------- problem constants ----------------
// B=4, C=3, H=W=768, P=128, S=64, K=31, n_h=n_w=11, N=121
#define TOTAL   7077888          // 4*3*768*768
#define IMGHW   589824           // 768*768
#define NPIX    961              // 31*31

typedef unsigned long long u64;

// ---------------- device scratch ----------------
__device__ float g_basis[14 * NPIX];
__device__ float g_mask[NPIX];
__device__ float g_coeffs[121 * 14];
__device__ float g_kern[363 * NPIX];      // flipped+normalized PSFs, [n*3+c][31*31]
__device__ float g_xlin[TOTAL];           // (relu(x)+eps)^gamma
__device__ float g_acc[4 * TOTAL];        // 4 parity planes (zero-init .bss; only valid entries written)

__device__ __forceinline__ float hann128(int r) {
    return 0.5f * (1.0f - cosf((6.28318530717958647692f * (float)r) * 0.0078125f));
}

__device__ __forceinline__ double dpow_i(double x, int e) {
    double r = 1.0;
    for (int q = 0; q < e; q++) r *= x;
    return r;
}

// packed 2xfp32 FMA (sm_103a FFMA2)
__device__ __forceinline__ void ffma2(u64& acc, u64 k2, u64 w2) {
    asm("fma.rn.f32x2 %0, %1, %2, %0;" : "+l"(acc) : "l"(k2), "l"(w2));
}
__device__ __forceinline__ float u64lo(u64 v) { return __uint_as_float((unsigned)v); }
__device__ __forceinline__ float u64hi(u64 v) { return __uint_as_float((unsigned)(v >> 32)); }

// ---------------- stage 0: pupil basis ----------------
// CRITICAL: replicate numpy's exact IEEE op sequence (no FMA contraction!) — 16 pixels
// sit EXACTLY on r2==1 (9-12-15 triple); membership decided by last-ulp rounding.
__global__ void basis_kernel() {
    __shared__ float red[1024];
    int t = threadIdx.x;
    bool act = (t < NPIX);
    int i = t / 31, j = t % 31;

    double step = 2.0 / 30.0;
    double x = 0.0, y = 0.0;
    float m = 0.0f;
    if (act) {
        x = (j == 30) ? 1.0 : __dadd_rn(__dmul_rn((double)j, step), -1.0);
        y = (i == 30) ? 1.0 : __dadd_rn(__dmul_rn((double)i, step), -1.0);
        double r2 = __dadd_rn(__dmul_rn(x, x), __dmul_rn(y, y));
        m = (r2 <= 1.0) ? 1.0f : 0.0f;
        g_mask[t] = m;
    }
    red[t] = act ? m : 0.0f;
    __syncthreads();
    for (int s = 512; s > 0; s >>= 1) {
        if (t < s) red[t] += red[t + s];
        __syncthreads();
    }
    float mc = red[0];
    __syncthreads();

    int z = 0;
    for (int deg = 1; deg <= 4; deg++) {
        for (int k = 0; k <= deg; k++) {
            float bb = 0.0f;
            if (act) bb = (float)(dpow_i(x, deg - k) * dpow_i(y, k)) * m;
            red[t] = bb * bb;
            __syncthreads();
            for (int s = 512; s > 0; s >>= 1) {
                if (t < s) red[t] += red[t + s];
                __syncthreads();
            }
            float rms = sqrtf(red[0] / mc) + 1e-8f;
            __syncthreads();
            if (act) g_basis[z * NPIX + t] = bb / rms;
            z++;
        }
    }
}

// ---------------- stage 1: MLP -> zernike coeffs ----------------
__global__ void mlp_kernel(const float* __restrict__ w1, const float* __restrict__ b1,
                           const float* __restrict__ w2, const float* __restrict__ b2,
                           const float* __restrict__ w3, const float* __restrict__ b3) {
    __shared__ float s1[64], s2[64];
    int n = blockIdx.x;
    int t = threadIdx.x;
    int iy = n / 11, jx = n % 11;
    float cy = (float)((((double)(iy * 64) + 64.0) / 768.0) * 2.0 - 1.0);
    float cx = (float)((((double)(jx * 64) + 64.0) / 768.0) * 2.0 - 1.0);

    float h = tanhf(cy * w1[t] + cx * w1[64 + t] + b1[t]);
    s1[t] = h;
    __syncthreads();
    float a = b2[t];
    for (int k = 0; k < 64; k++) a += s1[k] * w2[k * 64 + t];
    s2[t] = tanhf(a);
    __syncthreads();
    if (t < 14) {
        float o = b3[t];
        for (int k = 0; k < 64; k++) o += s2[k] * w3[k * 14 + t];
        g_coeffs[n * 14 + t] = o;
    }
}

// ---------------- stage 2: PSF via 31x31 separable DFT ----------------
__global__ void psf_kernel() {
    __shared__ float fre[NPIX], fim[NPIX], Gre[NPIX], Gim[NPIX];
    __shared__ float twr[31], twi[31];
    __shared__ float red[1024];
    int t = threadIdx.x;
    bool act = (t < NPIX);
    int blk = blockIdx.x;            // n*3 + c
    int n = blk / 3, c = blk % 3;

    if (t < 31) {
        float ang = -6.28318530717958647692f * (float)t / 31.0f;
        twr[t] = cosf(ang);
        twi[t] = sinf(ang);
    }
    float wl = 0.53f / ((c == 0) ? 0.61f : ((c == 1) ? 0.53f : 0.47f));

    if (act) {
        float ph = 0.0f;
        const float* cf = &g_coeffs[n * 14];
#pragma unroll
        for (int z = 0; z < 14; z++) ph = fmaf(cf[z], g_basis[z * NPIX + t], ph);
        float th = 6.28318530717958647692f * (wl * ph);
        float sn, cs;
        sincosf(th, &sn, &cs);
        float m = g_mask[t];
        fre[t] = m * cs;
        fim[t] = m * sn;
    }
    __syncthreads();

    int u = t / 31, v = t % 31;
    if (act) {
        float gr = 0.0f, gi = 0.0f;
        int m2 = 0;
        for (int i2 = 0; i2 < 31; i2++) {
            float tr = twr[m2], ti = twi[m2];
            float ar = fre[i2 * 31 + v], ai = fim[i2 * 31 + v];
            gr = fmaf(ar, tr, gr); gr = fmaf(-ai, ti, gr);
            gi = fmaf(ar, ti, gi); gi = fmaf(ai, tr, gi);
            m2 += u; if (m2 >= 31) m2 -= 31;
        }
        Gre[t] = gr; Gim[t] = gi;
    }
    __syncthreads();

    float mag = 0.0f;
    if (act) {
        float fr = 0.0f, fi = 0.0f;
        int m2 = 0;
        for (int j2 = 0; j2 < 31; j2++) {
            float tr = twr[m2], ti = twi[m2];
            float gr = Gre[u * 31 + j2], gi = Gim[u * 31 + j2];
            fr = fmaf(gr, tr, fr); fr = fmaf(-gi, ti, fr);
            fi = fmaf(gr, ti, fi); fi = fmaf(gi, tr, fi);
            m2 += v; if (m2 >= 31) m2 -= 31;
        }
        mag = fr * fr + fi * fi;
    }
    red[t] = act ? mag : 0.0f;
    __syncthreads();
    for (int s = 512; s > 0; s >>= 1) {
        if (t < s) red[t] += red[t + s];
        __syncthreads();
    }
    float inv = 1.0f / (red[0] + 1e-6f);
    if (act) {
        int pu = u + 15; if (pu >= 31) pu -= 31;
        int pv = v + 15; if (pv >= 31) pv -= 31;
        g_kern[blk * NPIX + (30 - pu) * 31 + (30 - pv)] = mag * inv;
    }
}

// ---------------- stage 3: gamma-linearize ----------------
__global__ void prep_kernel(const float* __restrict__ x, const float* __restrict__ gp) {
    int id = blockIdx.x * blockDim.x + threadIdx.x;
    if (id >= TOTAL) return;
    float g = *gp;
    float v = x[id];
    g_xlin[id] = powf(fmaxf(v, 0.0f) + 1e-6f, g);
}

// ---------------- stage 4: 31x31 depthwise conv, 16 rows/thread, FFMA2 ----------------
// Block = full 128x32 tile (grid 1452 x 4 col-tiles). Thread = 16 rows x 1 col.
// Even taps -> A[j]=(out[2j],out[2j+1]); odd taps -> O[j]=(out[2j-1],out[2j]),
// both consuming the same even-aligned input pairs. Window: 23 u64, ring-16.
__global__ void __launch_bounds__(256) conv_kernel() {
    __shared__ __align__(16) float sInT[62 * 158];   // [col][row] transposed, 39.2 KB
    __shared__ __align__(16) float2 sKd[31 * 32];    // duplicated taps (k,k), [dc][dr], 7.9 KB

    int id = blockIdx.x;
    int tile = id & 3;
    int pcc = id >> 2;
    int c = pcc % 3;
    int t2 = pcc / 3;
    int n = t2 % 121;
    int b = t2 / 121;
    int ip = n / 11, jp = n % 11;
    int C0 = tile << 5;          // 0,32,64,96
    int tid = threadIdx.x;

    const float* gk = g_kern + (n * 3 + c) * NPIX;
    for (int q = tid; q < NPIX; q += 256) {
        int dr = q / 31, dc2 = q - dr * 31;
        float k = gk[q];
        sKd[dc2 * 32 + dr] = make_float2(k, k);
    }

    const float* gxp = g_xlin + (size_t)(b * 3 + c) * IMGHW;
    for (int q = tid; q < 158 * 62; q += 256) {
        int rr = q / 62;
        int cc = q - rr * 62;
        int sy = rr - 15;        // patch row (block covers all 128 rows)
        int sx = C0 + cc - 15;
        float v = 0.0f;
        if ((unsigned)sy < 128u && (unsigned)sx < 128u)
            v = gxp[(ip * 64 + sy) * 768 + (jp * 64 + sx)];
        sInT[cc * 158 + rr] = v;
    }
    __syncthreads();

    int tx = tid & 31, ty = tid >> 5;    // ty 0..7 owns rows 16ty..16ty+15
    u64 A[8], O[9];
#pragma unroll
    for (int q = 0; q < 8; q++) A[q] = 0;
#pragma unroll
    for (int q = 0; q < 9; q++) O[q] = 0;

#pragma unroll 1
    for (int dc = 0; dc < 31; ++dc) {
        const u64* colp = (const u64*)(sInT + (tx + dc) * 158) + ty * 8;
        const u64* kp = (const u64*)(sKd + dc * 32);
        u64 pe[16];
#pragma unroll
        for (int j = 0; j < 9; j++) pe[j] = colp[j];

#pragma unroll
        for (int d = 0; d < 15; d++) {
            u64 ke = kp[2 * d];
#pragma unroll
            for (int j = 0; j < 8; j++) ffma2(A[j], ke, pe[(d + j) & 15]);
            u64 ko = kp[2 * d + 1];
#pragma unroll
            for (int j = 0; j < 9; j++) ffma2(O[j], ko, pe[(d + j) & 15]);
            if (d < 14) pe[(d + 9) & 15] = colp[d + 9];
        }
        {
            u64 ke = kp[30];     // final even tap dr=30 (d=15): uses pe[15..22]
#pragma unroll
            for (int j = 0; j < 8; j++) ffma2(A[j], ke, pe[(15 + j) & 15]);
        }
    }

    // recombine: out[2j] = A[j].lo + O[j].hi ; out[2j+1] = A[j].hi + O[j+1].lo
    int plane = ((ip & 1) << 1) | (jp & 1);
    float hc = hann128(C0 + tx);
    int gx0 = jp * 64 + C0 + tx;
    float* outp = g_acc + (size_t)plane * TOTAL + (size_t)(b * 3 + c) * IMGHW;
#pragma unroll
    for (int j = 0; j < 8; j++) {
        int pr0 = ty * 16 + 2 * j;
        float o0 = u64lo(A[j]) + u64hi(O[j]);
        float o1 = u64hi(A[j]) + u64lo(O[j + 1]);
        outp[(ip * 64 + pr0) * 768 + gx0]     = o0 * (hann128(pr0) * hc);
        outp[(ip * 64 + pr0 + 1) * 768 + gx0] = o1 * (hann128(pr0 + 1) * hc);
    }
}

// ---------------- stage 5: gather planes, window-normalize, inverse gamma ----------------
__global__ void fin_kernel(float* __restrict__ out, const float* __restrict__ gp) {
    int id = blockIdx.x * blockDim.x + threadIdx.x;
    if (id >= TOTAL) return;
    float ig = 1.0f / (*gp);
    int xcol = id % 768;
    int y = (id / 768) % 768;

    float ny = 0.0f, nx = 0.0f;
    int i1 = y >> 6;
    if (i1 <= 10) ny += hann128(y - i1 * 64);
    if (i1 >= 1)  ny += hann128(y - (i1 - 1) * 64);
    int j1 = xcol >> 6;
    if (j1 <= 10) nx += hann128(xcol - j1 * 64);
    if (j1 >= 1)  nx += hann128(xcol - (j1 - 1) * 64);

    float s = g_acc[id] + g_acc[TOTAL + id] + g_acc[2 * TOTAL + id] + g_acc[3 * TOTAL + id];
    float v = s / (ny * nx + 1e-6f);
    out[id] = powf(fmaxf(v, 0.0f) + 1e-6f, ig);
}

// ---------------- launch ----------------
extern "C" void kernel_launch(void* const* d_in, const int* in_sizes, int n_in,
                              void* d_out, int out_size) {
    const float* x  = (const float*)d_in[0];
    const float* w1 = (const float*)d_in[1];
    const float* b1 = (const float*)d_in[2];
    const float* w2 = (const float*)d_in[3];
    const float* b2 = (const float*)d_in[4];
    const float* w3 = (const float*)d_in[5];
    const float* b3 = (const float*)d_in[6];
    const float* gp = (const float*)d_in[7];
    float* out = (float*)d_out;

    basis_kernel<<<1, 1024>>>();
    mlp_kernel<<<121, 64>>>(w1, b1, w2, b2, w3, b3);
    psf_kernel<<<363, 1024>>>();
    prep_kernel<<<(TOTAL + 255) / 256, 256>>>(x, gp);
    conv_kernel<<<5808, 256>>>();
    fin_kernel<<<(TOTAL + 255) / 256, 256>>>(out, gp);
}